// round 1
// baseline (speedup 1.0000x reference)
#include <cuda_runtime.h>
#include <math.h>

// ---------------------------------------------------------------------------
// Problem constants (fixed shapes from the reference)
// ---------------------------------------------------------------------------
#define BB     8
#define NN     3136          // 56*56
#define HH_    56
#define WW_    56
#define DM     512
#define NH     4
#define HQ     128           // head qk dim
#define HV     256           // head v dim
#define CH     64            // chunk
#define NCH    49            // NN / CH
#define MROWS  (BB*NN)       // 25088

// ---------------------------------------------------------------------------
// Scratch (device globals; no allocations allowed)
// ---------------------------------------------------------------------------
static __device__ float g_xs   [MROWS*DM];     // conv+silu output
static __device__ float g_qkv  [MROWS*2048];   // q(512) k(512) v(1024)
static __device__ float g_g    [MROWS*1024];   // silu(gate)
static __device__ float g_gklat[MROWS*16];     // low-rank latent
static __device__ float g_gk   [MROWS*1024];   // gk_f(512) gk_b(512), logsig/16
static __device__ float g_of   [MROWS*1024];   // fwd GLA out  [(b*4+h)*NN+t]*256+v
static __device__ float g_ob   [MROWS*1024];   // bwd GLA out
static __device__ float g_oc   [MROWS*1024];   // combined (n, h*256+v)

__device__ __forceinline__ float sigm(float x){ return 1.f/(1.f+expf(-x)); }

// ---------------------------------------------------------------------------
// 1) depthwise 3x3 conv (SAME) + SiLU.  block = one (b,n) pixel, 512 threads=c
// ---------------------------------------------------------------------------
__global__ void __launch_bounds__(512) conv_silu_k(const float* __restrict__ x,
                                                   const float* __restrict__ w)
{
    int bn = blockIdx.x;
    int b  = bn / NN, n = bn % NN;
    int y  = n / WW_, xx = n % WW_;
    int c  = threadIdx.x;
    float wr[9];
#pragma unroll
    for (int i = 0; i < 9; ++i) wr[i] = w[c*9 + i];
    float acc = 0.f;
#pragma unroll
    for (int ky = 0; ky < 3; ++ky) {
        int yy = y + ky - 1;
        if (yy < 0 || yy >= HH_) continue;
#pragma unroll
        for (int kx = 0; kx < 3; ++kx) {
            int xc = xx + kx - 1;
            if (xc < 0 || xc >= WW_) continue;
            acc += x[(b*NN + yy*WW_ + xc)*DM + c] * wr[ky*3 + kx];
        }
    }
    g_xs[bn*DM + c] = acc * sigm(acc);
}

// ---------------------------------------------------------------------------
// 2) SGEMM (NT): C[m,n] = sum_k A[m,k]*Bw[n,k].  128x128 tile, BK=16,
//    256 threads, 8x8 micro-tile.  EPI: 0=none, 1=bias+silu
// ---------------------------------------------------------------------------
template<int EPI>
__global__ void __launch_bounds__(256) sgemm_nt_k(const float* __restrict__ A,
                                                  const float* __restrict__ Bw,
                                                  const float* __restrict__ bias,
                                                  float* __restrict__ C,
                                                  int M, int Nc, int K)
{
    __shared__ float As[16][132];
    __shared__ float Bs[16][132];
    int n0 = blockIdx.x * 128, m0 = blockIdx.y * 128;
    int tid = threadIdx.x;
    int tx = tid & 15, ty = tid >> 4;
    int lr = tid >> 2;            // 0..63
    int lk = (tid & 3) << 2;      // 0,4,8,12

    float acc[8][8];
#pragma unroll
    for (int i = 0; i < 8; ++i)
#pragma unroll
        for (int j = 0; j < 8; ++j) acc[i][j] = 0.f;

    for (int k0 = 0; k0 < K; k0 += 16) {
#pragma unroll
        for (int rr = 0; rr < 2; ++rr) {
            int row = lr + rr*64;
            float4 av = *(const float4*)&A [(m0+row)*K + k0 + lk];
            As[lk+0][row] = av.x; As[lk+1][row] = av.y;
            As[lk+2][row] = av.z; As[lk+3][row] = av.w;
            float4 bv = *(const float4*)&Bw[(n0+row)*K + k0 + lk];
            Bs[lk+0][row] = bv.x; Bs[lk+1][row] = bv.y;
            Bs[lk+2][row] = bv.z; Bs[lk+3][row] = bv.w;
        }
        __syncthreads();
#pragma unroll
        for (int kk = 0; kk < 16; ++kk) {
            float a[8], b[8];
            *(float4*)&a[0] = *(const float4*)&As[kk][ty*8];
            *(float4*)&a[4] = *(const float4*)&As[kk][ty*8+4];
            *(float4*)&b[0] = *(const float4*)&Bs[kk][tx*8];
            *(float4*)&b[4] = *(const float4*)&Bs[kk][tx*8+4];
#pragma unroll
            for (int i = 0; i < 8; ++i)
#pragma unroll
                for (int j = 0; j < 8; ++j) acc[i][j] += a[i]*b[j];
        }
        __syncthreads();
    }
#pragma unroll
    for (int i = 0; i < 8; ++i) {
        int m = m0 + ty*8 + i;
#pragma unroll
        for (int j = 0; j < 8; ++j) {
            int n = n0 + tx*8 + j;
            float v = acc[i][j];
            if (EPI == 1) { v += bias[n]; v = v * (1.f/(1.f+expf(-v))); }
            C[m*Nc + n] = v;
        }
    }
}

// ---------------------------------------------------------------------------
// 3) gk low-rank stage 1: lat[m,0:16] = xs[m,:] @ gk_w1.T
// ---------------------------------------------------------------------------
__global__ void __launch_bounds__(256) gk1_k(const float* __restrict__ w1)
{
    __shared__ float w1s[16*DM];
    int tid = threadIdx.x;
    for (int i = tid; i < 16*DM; i += 256) w1s[i] = w1[i];
    __syncthreads();
    int m0 = blockIdx.x * 16;
    int r  = tid >> 4, j = tid & 15;
    const float4* xr = (const float4*)&g_xs[(m0+r)*DM];
    const float4* wv = (const float4*)&w1s[j*DM];
    float acc = 0.f;
#pragma unroll 4
    for (int k = 0; k < DM/4; ++k) {
        float4 xv = xr[k], w4 = wv[k];
        acc += xv.x*w4.x + xv.y*w4.y + xv.z*w4.z + xv.w*w4.w;
    }
    g_gklat[(m0+r)*16 + j] = acc;
}

// ---------------------------------------------------------------------------
// 4) gk stage 2: gk[m,j] = logsigmoid(lat @ w2.T + b2)/16
// ---------------------------------------------------------------------------
__global__ void __launch_bounds__(256) gk2_k(const float* __restrict__ w2,
                                             const float* __restrict__ b2)
{
    __shared__ float lat[64*16];
    int m0 = blockIdx.y * 64;
    int j  = blockIdx.x * 256 + threadIdx.x;
    for (int i = threadIdx.x; i < 64*16; i += 256) lat[i] = g_gklat[m0*16 + i];
    __syncthreads();
    float w[16];
#pragma unroll
    for (int i = 0; i < 16; ++i) w[i] = w2[j*16 + i];
    float bb = b2[j];
    for (int r = 0; r < 64; ++r) {
        float xv = bb;
#pragma unroll
        for (int i = 0; i < 16; ++i) xv += lat[r*16 + i]*w[i];
        float ls = fminf(xv, 0.f) - log1pf(expf(-fabsf(xv)));
        g_gk[(m0+r)*1024 + j] = ls * (1.f/16.f);
    }
}

// ---------------------------------------------------------------------------
// 5) Chunked GLA. grid = (vslice 4, b*h 32, dir 2).  256 threads.
//    State S[128 x 64] kept in SMEM across 49 sequential chunks.
// ---------------------------------------------------------------------------
#define GLA_SMEM_FLOATS (3*64*132 + 2*64*68 + 128*68 + 128)
#define GLA_SMEM_BYTES  (GLA_SMEM_FLOATS*4)

__global__ void __launch_bounds__(256, 1) gla_k()
{
    extern __shared__ float sm[];
    float* sq  = sm;                  // 64 x 132  (q -> qe)
    float* sk  = sq  + 64*132;        // 64 x 132  (k -> kd)
    float* sg  = sk  + 64*132;        // 64 x 132  (gk -> cumsum b)
    float* sv  = sg  + 64*132;        // 64 x 68
    float* sA  = sv  + 64*68;         // 64 x 68
    float* sS  = sA  + 64*68;         // 128 x 68  (state)
    float* sbt = sS  + 128*68;        // 128       (btot)

    const int vs  = blockIdx.x;
    const int bh  = blockIdx.y;
    const int dir = blockIdx.z;
    const int b   = bh >> 2;
    const int tid = threadIdx.x;
    const int h   = bh & 3;
    const float scale = 0.088388347648318447f;  // 128^-0.5

    for (int i = tid; i < 128*68; i += 256) sS[i] = 0.f;
    __syncthreads();

    const int qoff = h*HQ;
    const int koff = 512 + h*HQ;
    const int voff = 1024 + h*HV + vs*64;
    const int goff = dir*512 + h*HQ;
    const int rowb = b*NN;
    float* const outp = dir ? g_ob : g_of;

    for (int c = 0; c < NCH; ++c) {
        // ---- load q/k/gk (64x128) and v (64x64), vectorized ----
        for (int i = tid; i < 64*32; i += 256) {
            int t  = i >> 5, d4 = (i & 31) * 4;
            int tg = dir ? (NN-1 - (c*64 + t)) : (c*64 + t);
            int r  = rowb + tg;
            *(float4*)&sq[t*132 + d4] = *(const float4*)&g_qkv[r*2048 + qoff + d4];
            *(float4*)&sk[t*132 + d4] = *(const float4*)&g_qkv[r*2048 + koff + d4];
            *(float4*)&sg[t*132 + d4] = *(const float4*)&g_gk [r*1024 + goff + d4];
        }
        for (int i = tid; i < 64*16; i += 256) {
            int t  = i >> 4, v4 = (i & 15) * 4;
            int tg = dir ? (NN-1 - (c*64 + t)) : (c*64 + t);
            *(float4*)&sv[t*68 + v4] = *(const float4*)&g_qkv[(rowb+tg)*2048 + voff + v4];
        }
        __syncthreads();

        // ---- cumsum of gk along t (one thread per d) ----
        if (tid < 128) {
            float run = 0.f;
            for (int t = 0; t < 64; ++t) { run += sg[t*132 + tid]; sg[t*132 + tid] = run; }
            sbt[tid] = run;
        }
        __syncthreads();

        // ---- qe = q*exp(b)*scale ; kd = k*exp(-b) ----
        for (int i = tid; i < 64*128; i += 256) {
            int t = i >> 7, d = i & 127;
            float bv = sg[t*132 + d];
            sq[t*132 + d] *= expf(bv) * scale;
            sk[t*132 + d] *= expf(-bv);
        }
        __syncthreads();

        // ---- A = qe @ kd^T (64x64), masked lower-tri ----
        {
            int tx = tid & 15, ty = tid >> 4;
            float acc[4][4];
#pragma unroll
            for (int i = 0; i < 4; ++i)
#pragma unroll
                for (int j = 0; j < 4; ++j) acc[i][j] = 0.f;
            for (int d4 = 0; d4 < 32; ++d4) {
                float4 a[4], bq[4];
#pragma unroll
                for (int i = 0; i < 4; ++i) a[i]  = *(const float4*)&sq[(ty*4+i)*132 + d4*4];
#pragma unroll
                for (int j = 0; j < 4; ++j) bq[j] = *(const float4*)&sk[(tx*4+j)*132 + d4*4];
#pragma unroll
                for (int i = 0; i < 4; ++i)
#pragma unroll
                    for (int j = 0; j < 4; ++j)
                        acc[i][j] += a[i].x*bq[j].x + a[i].y*bq[j].y
                                   + a[i].z*bq[j].z + a[i].w*bq[j].w;
            }
#pragma unroll
            for (int i = 0; i < 4; ++i)
#pragma unroll
                for (int j = 0; j < 4; ++j) {
                    int t = ty*4+i, s = tx*4+j;
                    sA[t*68 + s] = (s <= t) ? acc[i][j] : 0.f;
                }
        }
        __syncthreads();

        // ---- o = A@v + qe@S -> global ----
        {
            int tx = tid & 15, ty = tid >> 4;
            float4 acc[4];
#pragma unroll
            for (int i = 0; i < 4; ++i) { acc[i].x=0.f; acc[i].y=0.f; acc[i].z=0.f; acc[i].w=0.f; }
            for (int s = 0; s < 64; ++s) {
                float4 vv = *(const float4*)&sv[s*68 + tx*4];
#pragma unroll
                for (int i = 0; i < 4; ++i) {
                    float a = sA[(ty*4+i)*68 + s];
                    acc[i].x += a*vv.x; acc[i].y += a*vv.y;
                    acc[i].z += a*vv.z; acc[i].w += a*vv.w;
                }
            }
            for (int d = 0; d < 128; ++d) {
                float4 sr = *(const float4*)&sS[d*68 + tx*4];
#pragma unroll
                for (int i = 0; i < 4; ++i) {
                    float a = sq[(ty*4+i)*132 + d];
                    acc[i].x += a*sr.x; acc[i].y += a*sr.y;
                    acc[i].z += a*sr.z; acc[i].w += a*sr.w;
                }
            }
#pragma unroll
            for (int i = 0; i < 4; ++i) {
                int t  = ty*4+i;
                int tg = dir ? (NN-1 - (c*64 + t)) : (c*64 + t);
                *(float4*)&outp[(bh*NN + tg)*256 + vs*64 + tx*4] = acc[i];
            }
        }
        __syncthreads();

        // ---- S = exp(btot)*(S + kd^T @ v) ----
        {
            int tvx = tid & 15, tvy = tid >> 4;
            float4 acc[8];
#pragma unroll
            for (int i = 0; i < 8; ++i) { acc[i].x=0.f; acc[i].y=0.f; acc[i].z=0.f; acc[i].w=0.f; }
            for (int t = 0; t < 64; ++t) {
                float4 vv = *(const float4*)&sv[t*68 + tvx*4];
#pragma unroll
                for (int i = 0; i < 8; ++i) {
                    float kk = sk[t*132 + tvy*8 + i];
                    acc[i].x += kk*vv.x; acc[i].y += kk*vv.y;
                    acc[i].z += kk*vv.z; acc[i].w += kk*vv.w;
                }
            }
#pragma unroll
            for (int i = 0; i < 8; ++i) {
                int d = tvy*8 + i;
                float e = expf(sbt[d]);
                float4* Sp = (float4*)&sS[d*68 + tvx*4];
                float4 o = *Sp;
                o.x = e*(o.x + acc[i].x); o.y = e*(o.y + acc[i].y);
                o.z = e*(o.z + acc[i].z); o.w = e*(o.w + acc[i].w);
                *Sp = o;
            }
        }
        __syncthreads();
    }
}

// ---------------------------------------------------------------------------
// 6) combine: rmsnorm(o_f)+rmsnorm(o_b), * silu(gate), repack to (n, h*256+v)
// ---------------------------------------------------------------------------
__global__ void __launch_bounds__(256) combine_k(const float* __restrict__ gnw,
                                                 const float* __restrict__ lnw)
{
    __shared__ float red[16];
    int idx = blockIdx.x;            // bh*NN + t
    int bh  = idx / NN, t = idx % NN;
    int b   = bh >> 2,  h = bh & 3;
    int v   = threadIdx.x;
    float of = g_of[idx*256 + v];
    float ob = g_ob[idx*256 + v];
    float sf = of*of, sb = ob*ob;
#pragma unroll
    for (int o = 16; o > 0; o >>= 1) {
        sf += __shfl_xor_sync(0xffffffffu, sf, o);
        sb += __shfl_xor_sync(0xffffffffu, sb, o);
    }
    int w = v >> 5, l = v & 31;
    if (l == 0) { red[w] = sf; red[8+w] = sb; }
    __syncthreads();
    float tf = 0.f, tb = 0.f;
#pragma unroll
    for (int i = 0; i < 8; ++i) { tf += red[i]; tb += red[8+i]; }
    float inf_ = rsqrtf(tf*(1.f/256.f) + 1e-5f);
    float inb_ = rsqrtf(tb*(1.f/256.f) + 1e-5f);
    float o = of*inf_*gnw[v] + ob*inb_*lnw[v];
    int gi = (b*NN + t)*1024 + h*256 + v;
    g_oc[gi] = o * g_g[gi];
}

// ---------------------------------------------------------------------------
// launcher
// ---------------------------------------------------------------------------
extern "C" void kernel_launch(void* const* d_in, const int* in_sizes, int n_in,
                              void* d_out, int out_size)
{
    const float* x     = (const float*)d_in[0];
    const float* convw = (const float*)d_in[1];
    const float* qkvw  = (const float*)d_in[2];
    const float* gkw1  = (const float*)d_in[3];
    const float* gkw2  = (const float*)d_in[4];
    const float* gkb2  = (const float*)d_in[5];
    const float* gw    = (const float*)d_in[6];
    const float* gb    = (const float*)d_in[7];
    const float* gnw   = (const float*)d_in[8];
    const float* lnw   = (const float*)d_in[9];
    const float* ow    = (const float*)d_in[10];
    float* out = (float*)d_out;

    cudaFuncSetAttribute(gla_k, cudaFuncAttributeMaxDynamicSharedMemorySize, GLA_SMEM_BYTES);

    float *p_xs, *p_qkv, *p_g, *p_oc;
    cudaGetSymbolAddress((void**)&p_xs,  g_xs);
    cudaGetSymbolAddress((void**)&p_qkv, g_qkv);
    cudaGetSymbolAddress((void**)&p_g,   g_g);
    cudaGetSymbolAddress((void**)&p_oc,  g_oc);

    conv_silu_k<<<MROWS, 512>>>(x, convw);
    sgemm_nt_k<0><<<dim3(2048/128, MROWS/128), 256>>>(p_xs, qkvw, nullptr, p_qkv, MROWS, 2048, DM);
    sgemm_nt_k<1><<<dim3(1024/128, MROWS/128), 256>>>(p_xs, gw, gb, p_g, MROWS, 1024, DM);
    gk1_k<<<MROWS/16, 256>>>(gkw1);
    gk2_k<<<dim3(4, MROWS/64), 256>>>(gkw2, gkb2);
    gla_k<<<dim3(4, BB*NH, 2), 256, GLA_SMEM_BYTES>>>();
    combine_k<<<BB*NH*NN, 256>>>(gnw, lnw);
    sgemm_nt_k<0><<<dim3(512/128, MROWS/128), 256>>>(p_oc, ow, nullptr, out, MROWS, 512, 1024);
}

// round 7
// speedup vs baseline: 1.5043x; 1.5043x over previous
#include <cuda_runtime.h>
#include <cuda_bf16.h>
#include <math.h>
#include <stdint.h>

// ---------------------------------------------------------------------------
// Problem constants
// ---------------------------------------------------------------------------
#define BB     8
#define NN     3136
#define HH_    56
#define WW_    56
#define DM     512
#define NH     4
#define HQ     128
#define HV     256
#define CH     64
#define NCH    49
#define MROWS  (BB*NN)       // 25088

// ---------------------------------------------------------------------------
// Scratch
// ---------------------------------------------------------------------------
static __device__ float g_xs   [MROWS*DM];
static __device__ __nv_bfloat16 g_xs_h[MROWS*DM];
static __device__ __nv_bfloat16 g_xs_l[MROWS*DM];
static __device__ float g_qkv  [MROWS*2048];
static __device__ float g_g    [MROWS*1024];
static __device__ float g_gklat[MROWS*16];
static __device__ float g_gk   [MROWS*1024];
static __device__ float g_of   [MROWS*1024];
static __device__ float g_ob   [MROWS*1024];
static __device__ __nv_bfloat16 g_oc_h[MROWS*1024];
static __device__ __nv_bfloat16 g_oc_l[MROWS*1024];
static __device__ __nv_bfloat16 g_wq_h[2048*512], g_wq_l[2048*512];
static __device__ __nv_bfloat16 g_wg_h[1024*512], g_wg_l[1024*512];
static __device__ __nv_bfloat16 g_wo_h[512*1024], g_wo_l[512*1024];

__device__ __forceinline__ float sigm(float x){ return 1.f/(1.f+expf(-x)); }

__device__ __forceinline__ uint32_t smem_u32(const void* p) {
    uint32_t a;
    asm("{ .reg .u64 t; cvta.to.shared.u64 t, %1; cvt.u32.u64 %0, t; }" : "=r"(a) : "l"(p));
    return a;
}
__device__ __forceinline__ void cp16(uint32_t dst, const void* src) {
    asm volatile("cp.async.cg.shared.global [%0], [%1], 16;" :: "r"(dst), "l"(src));
}
#define CP_COMMIT() asm volatile("cp.async.commit_group;" ::: "memory")
#define CP_WAIT0()  asm volatile("cp.async.wait_group 0;" ::: "memory")
#define CP_WAIT1()  asm volatile("cp.async.wait_group 1;" ::: "memory")

__device__ __forceinline__ void ldsm4(uint32_t* r, uint32_t addr) {
    asm volatile("ldmatrix.sync.aligned.m8n8.x4.shared.b16 {%0,%1,%2,%3}, [%4];"
        : "=r"(r[0]), "=r"(r[1]), "=r"(r[2]), "=r"(r[3]) : "r"(addr));
}
__device__ __forceinline__ void mma16816(float* c, const uint32_t* a, uint32_t b0, uint32_t b1) {
    asm volatile("mma.sync.aligned.m16n8k16.row.col.f32.bf16.bf16.f32 "
        "{%0,%1,%2,%3}, {%4,%5,%6,%7}, {%8,%9}, {%0,%1,%2,%3};"
        : "+f"(c[0]), "+f"(c[1]), "+f"(c[2]), "+f"(c[3])
        : "r"(a[0]), "r"(a[1]), "r"(a[2]), "r"(a[3]), "r"(b0), "r"(b1));
}

extern __shared__ char s_dyn[];

// ---------------------------------------------------------------------------
// 1) depthwise 3x3 conv + SiLU, emit fp32 + bf16 hi/lo
// ---------------------------------------------------------------------------
__global__ void __launch_bounds__(512) conv_silu_k(const float* __restrict__ x,
                                                   const float* __restrict__ w)
{
    int bn = blockIdx.x;
    int b  = bn / NN, n = bn % NN;
    int y  = n / WW_, xx = n % WW_;
    int c  = threadIdx.x;
    float wr[9];
#pragma unroll
    for (int i = 0; i < 9; ++i) wr[i] = w[c*9 + i];
    float acc = 0.f;
#pragma unroll
    for (int ky = 0; ky < 3; ++ky) {
        int yy = y + ky - 1;
        if (yy < 0 || yy >= HH_) continue;
#pragma unroll
        for (int kx = 0; kx < 3; ++kx) {
            int xc = xx + kx - 1;
            if (xc < 0 || xc >= WW_) continue;
            acc += x[(b*NN + yy*WW_ + xc)*DM + c] * wr[ky*3 + kx];
        }
    }
    float r = acc * sigm(acc);
    g_xs[bn*DM + c] = r;
    __nv_bfloat16 h = __float2bfloat16(r);
    g_xs_h[bn*DM + c] = h;
    g_xs_l[bn*DM + c] = __float2bfloat16(r - __bfloat162float(h));
}

// ---------------------------------------------------------------------------
// hi/lo conversion for weights
// ---------------------------------------------------------------------------
__global__ void __launch_bounds__(256) cvt_hilo_k(const float* __restrict__ s,
                                                  __nv_bfloat16* __restrict__ h,
                                                  __nv_bfloat16* __restrict__ l, int n)
{
    int i = blockIdx.x*256 + threadIdx.x;
    if (i < n) {
        float v = s[i];
        __nv_bfloat16 hh = __float2bfloat16(v);
        h[i] = hh;
        l[i] = __float2bfloat16(v - __bfloat162float(hh));
    }
}

// ---------------------------------------------------------------------------
// 2) bf16x3 GEMM (NT) via mma.sync m16n8k16.
//    CTA 128x128, 256 thr (8 warps = 4m x 2n, warp tile 32x64), K-chunk 64,
//    double-buffered cp.async, XOR-128B smem swizzle, ldmatrix fragments.
//    C = Ah.Bh + Ah.Bl + Al.Bh  (fp32 accum)
// ---------------------------------------------------------------------------
#define GEMM_SMEM (2*4*16384)     // 2 buffers x (Ah,Al,Bh,Bl) x 16KB

template<int EPI>
__global__ void __launch_bounds__(256, 1)
gemm128_k(const __nv_bfloat16* __restrict__ Ah, const __nv_bfloat16* __restrict__ Al,
          const __nv_bfloat16* __restrict__ Bh, const __nv_bfloat16* __restrict__ Bl,
          const float* __restrict__ bias, float* __restrict__ C, int Nc, int K)
{
    const int tid  = threadIdx.x;
    const int lane = tid & 31;
    const int wid  = tid >> 5;
    const int wm   = (wid & 3) * 32;     // warp m offset in tile
    const int wn   = (wid >> 2) * 64;    // warp n offset in tile
    const int n0 = blockIdx.x * 128, m0 = blockIdx.y * 128;
    const uint32_t sb = smem_u32(s_dyn);
    const int nk = K >> 6;

    float acc[2][8][4];
#pragma unroll
    for (int i = 0; i < 2; ++i)
#pragma unroll
        for (int j = 0; j < 8; ++j)
#pragma unroll
            for (int q = 0; q < 4; ++q) acc[i][j][q] = 0.f;

    // ---- loader: chunk kc -> buffer (kc&1) ----
    auto load_chunk = [&](int kc) {
        uint32_t tb = sb + (kc & 1) * 65536;
        int kb = kc << 6;
#pragma unroll
        for (int it = 0; it < 4; ++it) {
            int i = tid + it*256;            // 0..1023
            int row = i >> 3, seg = i & 7;
            uint32_t off = (uint32_t)(row*128 + seg*16);
            uint32_t sw = off ^ ((off >> 3) & 0x70);
            const __nv_bfloat16* pAh = Ah + (size_t)(m0 + row)*K + kb + seg*8;
            const __nv_bfloat16* pAl = Al + (size_t)(m0 + row)*K + kb + seg*8;
            const __nv_bfloat16* pBh = Bh + (size_t)(n0 + row)*K + kb + seg*8;
            const __nv_bfloat16* pBl = Bl + (size_t)(n0 + row)*K + kb + seg*8;
            cp16(tb +         sw, pAh);
            cp16(tb + 16384 + sw, pAl);
            cp16(tb + 32768 + sw, pBh);
            cp16(tb + 49152 + sw, pBl);
        }
    };

    load_chunk(0); CP_COMMIT();

    // per-lane ldmatrix address components
    const int aRow = lane & 15;                 // + wm + mt*16
    const int aKof = ((lane >> 4) & 1) * 16;    // byte offset within k16 (=32B)
    const int bRowL = (lane & 7) + ((lane & 16) ? 8 : 0);   // + wn + ntp*16
    const int bKof = (lane & 8) ? 16 : 0;

    for (int c = 0; c < nk; ++c) {
        if (c + 1 < nk) { load_chunk(c + 1); CP_COMMIT(); CP_WAIT1(); }
        else            { CP_WAIT0(); }
        __syncthreads();

        uint32_t tb = sb + (c & 1) * 65536;
#pragma unroll
        for (int ks = 0; ks < 4; ++ks) {
            const int kbyte = ks * 32;
            uint32_t aH[2][4], aL[2][4];
#pragma unroll
            for (int mt = 0; mt < 2; ++mt) {
                uint32_t off = (uint32_t)((wm + mt*16 + aRow) * 128 + kbyte + aKof);
                uint32_t sw = off ^ ((off >> 3) & 0x70);
                ldsm4(aH[mt], tb + sw);
                ldsm4(aL[mt], tb + 16384 + sw);
            }
#pragma unroll
            for (int ntp = 0; ntp < 4; ++ntp) {
                uint32_t off = (uint32_t)((wn + ntp*16 + bRowL) * 128 + kbyte + bKof);
                uint32_t sw = off ^ ((off >> 3) & 0x70);
                uint32_t bh[4], bl[4];
                ldsm4(bh, tb + 32768 + sw);
                ldsm4(bl, tb + 49152 + sw);
#pragma unroll
                for (int mt = 0; mt < 2; ++mt) {
                    mma16816(acc[mt][ntp*2+0], aH[mt], bh[0], bh[1]);
                    mma16816(acc[mt][ntp*2+1], aH[mt], bh[2], bh[3]);
                    mma16816(acc[mt][ntp*2+0], aH[mt], bl[0], bl[1]);
                    mma16816(acc[mt][ntp*2+1], aH[mt], bl[2], bl[3]);
                    mma16816(acc[mt][ntp*2+0], aL[mt], bh[0], bh[1]);
                    mma16816(acc[mt][ntp*2+1], aL[mt], bh[2], bh[3]);
                }
            }
        }
        __syncthreads();
    }

    // ---- epilogue ----
    const int rbase = m0 + wm + (lane >> 2);
    const int cbase = n0 + wn + (lane & 3) * 2;
#pragma unroll
    for (int mt = 0; mt < 2; ++mt) {
#pragma unroll
        for (int nt = 0; nt < 8; ++nt) {
            int col = cbase + nt*8;
#pragma unroll
            for (int half = 0; half < 2; ++half) {
                int row = rbase + mt*16 + half*8;
                float v0 = acc[mt][nt][half*2+0];
                float v1 = acc[mt][nt][half*2+1];
                if (EPI == 1) {
                    v0 += bias[col+0]; v0 *= sigm(v0);
                    v1 += bias[col+1]; v1 *= sigm(v1);
                }
                float2 vv; vv.x = v0; vv.y = v1;
                *(float2*)&C[(size_t)row*Nc + col] = vv;
            }
        }
    }
}

// ---------------------------------------------------------------------------
// 3) gk low-rank stage 1 (register-tiled)
// ---------------------------------------------------------------------------
__global__ void __launch_bounds__(256) gk1_k(const float* __restrict__ w1)
{
    __shared__ float w1s[16*DM];
    int tid = threadIdx.x;
    for (int i = tid; i < 16*DM; i += 256) w1s[i] = w1[i];
    __syncthreads();
    int m0 = blockIdx.x * 64;
    int j  = tid & 15, rg = tid >> 4;
    const float* xb = &g_xs[(m0 + rg*4)*DM];
    const float4* w4 = (const float4*)&w1s[j*DM];
    float a0 = 0.f, a1 = 0.f, a2 = 0.f, a3 = 0.f;
#pragma unroll 4
    for (int k = 0; k < DM/4; ++k) {
        float4 wv = w4[k];
        float4 x0 = *(const float4*)&xb[0*DM + k*4];
        float4 x1 = *(const float4*)&xb[1*DM + k*4];
        float4 x2 = *(const float4*)&xb[2*DM + k*4];
        float4 x3 = *(const float4*)&xb[3*DM + k*4];
        a0 += x0.x*wv.x + x0.y*wv.y + x0.z*wv.z + x0.w*wv.w;
        a1 += x1.x*wv.x + x1.y*wv.y + x1.z*wv.z + x1.w*wv.w;
        a2 += x2.x*wv.x + x2.y*wv.y + x2.z*wv.z + x2.w*wv.w;
        a3 += x3.x*wv.x + x3.y*wv.y + x3.z*wv.z + x3.w*wv.w;
    }
    g_gklat[(m0+rg*4+0)*16 + j] = a0;
    g_gklat[(m0+rg*4+1)*16 + j] = a1;
    g_gklat[(m0+rg*4+2)*16 + j] = a2;
    g_gklat[(m0+rg*4+3)*16 + j] = a3;
}

// ---------------------------------------------------------------------------
// 4) gk stage 2
// ---------------------------------------------------------------------------
__global__ void __launch_bounds__(256) gk2_k(const float* __restrict__ w2,
                                             const float* __restrict__ b2)
{
    __shared__ float lat[64*16];
    int m0 = blockIdx.y * 64;
    int j  = blockIdx.x * 256 + threadIdx.x;
    for (int i = threadIdx.x; i < 64*16; i += 256) lat[i] = g_gklat[m0*16 + i];
    __syncthreads();
    float w[16];
#pragma unroll
    for (int i = 0; i < 16; ++i) w[i] = w2[j*16 + i];
    float bb = b2[j];
    for (int r = 0; r < 64; ++r) {
        float xv = bb;
#pragma unroll
        for (int i = 0; i < 16; ++i) xv += lat[r*16 + i]*w[i];
        float ls = fminf(xv, 0.f) - log1pf(expf(-fabsf(xv)));
        g_gk[(m0+r)*1024 + j] = ls * (1.f/16.f);
    }
}

// ---------------------------------------------------------------------------
// 5) Chunked GLA (fp32, unchanged)
// ---------------------------------------------------------------------------
#define GLA_SMEM_FLOATS (3*64*132 + 2*64*68 + 128*68 + 128)
#define GLA_SMEM_BYTES  (GLA_SMEM_FLOATS*4)

__global__ void __launch_bounds__(256, 1) gla_k()
{
    float* sm = (float*)s_dyn;
    float* sq  = sm;
    float* sk  = sq  + 64*132;
    float* sg  = sk  + 64*132;
    float* sv  = sg  + 64*132;
    float* sA  = sv  + 64*68;
    float* sS  = sA  + 64*68;
    float* sbt = sS  + 128*68;

    const int vs  = blockIdx.x;
    const int bh  = blockIdx.y;
    const int dir = blockIdx.z;
    const int b   = bh >> 2;
    const int tid = threadIdx.x;
    const int h   = bh & 3;
    const float scale = 0.088388347648318447f;

    for (int i = tid; i < 128*68; i += 256) sS[i] = 0.f;
    __syncthreads();

    const int qoff = h*HQ;
    const int koff = 512 + h*HQ;
    const int voff = 1024 + h*HV + vs*64;
    const int goff = dir*512 + h*HQ;
    const int rowb = b*NN;
    float* const outp = dir ? g_ob : g_of;

    for (int c = 0; c < NCH; ++c) {
        for (int i = tid; i < 64*32; i += 256) {
            int t  = i >> 5, d4 = (i & 31) * 4;
            int tg = dir ? (NN-1 - (c*64 + t)) : (c*64 + t);
            int r  = rowb + tg;
            *(float4*)&sq[t*132 + d4] = *(const float4*)&g_qkv[r*2048 + qoff + d4];
            *(float4*)&sk[t*132 + d4] = *(const float4*)&g_qkv[r*2048 + koff + d4];
            *(float4*)&sg[t*132 + d4] = *(const float4*)&g_gk [r*1024 + goff + d4];
        }
        for (int i = tid; i < 64*16; i += 256) {
            int t  = i >> 4, v4 = (i & 15) * 4;
            int tg = dir ? (NN-1 - (c*64 + t)) : (c*64 + t);
            *(float4*)&sv[t*68 + v4] = *(const float4*)&g_qkv[(rowb+tg)*2048 + voff + v4];
        }
        __syncthreads();

        if (tid < 128) {
            float run = 0.f;
            for (int t = 0; t < 64; ++t) { run += sg[t*132 + tid]; sg[t*132 + tid] = run; }
            sbt[tid] = run;
        }
        __syncthreads();

        for (int i = tid; i < 64*128; i += 256) {
            int t = i >> 7, d = i & 127;
            float bv = sg[t*132 + d];
            sq[t*132 + d] *= expf(bv) * scale;
            sk[t*132 + d] *= expf(-bv);
        }
        __syncthreads();

        {
            int tx = tid & 15, ty = tid >> 4;
            float acc[4][4];
#pragma unroll
            for (int i = 0; i < 4; ++i)
#pragma unroll
                for (int j = 0; j < 4; ++j) acc[i][j] = 0.f;
            for (int d4 = 0; d4 < 32; ++d4) {
                float4 a[4], bq[4];
#pragma unroll
                for (int i = 0; i < 4; ++i) a[i]  = *(const float4*)&sq[(ty*4+i)*132 + d4*4];
#pragma unroll
                for (int j = 0; j < 4; ++j) bq[j] = *(const float4*)&sk[(tx*4+j)*132 + d4*4];
#pragma unroll
                for (int i = 0; i < 4; ++i)
#pragma unroll
                    for (int j = 0; j < 4; ++j)
                        acc[i][j] += a[i].x*bq[j].x + a[i].y*bq[j].y
                                   + a[i].z*bq[j].z + a[i].w*bq[j].w;
            }
#pragma unroll
            for (int i = 0; i < 4; ++i)
#pragma unroll
                for (int j = 0; j < 4; ++j) {
                    int t = ty*4+i, s = tx*4+j;
                    sA[t*68 + s] = (s <= t) ? acc[i][j] : 0.f;
                }
        }
        __syncthreads();

        {
            int tx = tid & 15, ty = tid >> 4;
            float4 acc[4];
#pragma unroll
            for (int i = 0; i < 4; ++i) { acc[i].x=0.f; acc[i].y=0.f; acc[i].z=0.f; acc[i].w=0.f; }
            for (int s = 0; s < 64; ++s) {
                float4 vv = *(const float4*)&sv[s*68 + tx*4];
#pragma unroll
                for (int i = 0; i < 4; ++i) {
                    float a = sA[(ty*4+i)*68 + s];
                    acc[i].x += a*vv.x; acc[i].y += a*vv.y;
                    acc[i].z += a*vv.z; acc[i].w += a*vv.w;
                }
            }
            for (int d = 0; d < 128; ++d) {
                float4 sr = *(const float4*)&sS[d*68 + tx*4];
#pragma unroll
                for (int i = 0; i < 4; ++i) {
                    float a = sq[(ty*4+i)*132 + d];
                    acc[i].x += a*sr.x; acc[i].y += a*sr.y;
                    acc[i].z += a*sr.z; acc[i].w += a*sr.w;
                }
            }
#pragma unroll
            for (int i = 0; i < 4; ++i) {
                int t  = ty*4+i;
                int tg = dir ? (NN-1 - (c*64 + t)) : (c*64 + t);
                *(float4*)&outp[(bh*NN + tg)*256 + vs*64 + tx*4] = acc[i];
            }
        }
        __syncthreads();

        {
            int tvx = tid & 15, tvy = tid >> 4;
            float4 acc[8];
#pragma unroll
            for (int i = 0; i < 8; ++i) { acc[i].x=0.f; acc[i].y=0.f; acc[i].z=0.f; acc[i].w=0.f; }
            for (int t = 0; t < 64; ++t) {
                float4 vv = *(const float4*)&sv[t*68 + tvx*4];
#pragma unroll
                for (int i = 0; i < 8; ++i) {
                    float kk = sk[t*132 + tvy*8 + i];
                    acc[i].x += kk*vv.x; acc[i].y += kk*vv.y;
                    acc[i].z += kk*vv.z; acc[i].w += kk*vv.w;
                }
            }
#pragma unroll
            for (int i = 0; i < 8; ++i) {
                int d = tvy*8 + i;
                float e = expf(sbt[d]);
                float4* Sp = (float4*)&sS[d*68 + tvx*4];
                float4 o = *Sp;
                o.x = e*(o.x + acc[i].x); o.y = e*(o.y + acc[i].y);
                o.z = e*(o.z + acc[i].z); o.w = e*(o.w + acc[i].w);
                *Sp = o;
            }
        }
        __syncthreads();
    }
}

// ---------------------------------------------------------------------------
// 6) combine: rmsnorm(o_f)+rmsnorm(o_b), * silu(gate), emit oc hi/lo bf16
// ---------------------------------------------------------------------------
__global__ void __launch_bounds__(256) combine_k(const float* __restrict__ gnw,
                                                 const float* __restrict__ lnw)
{
    __shared__ float red[16];
    int idx = blockIdx.x;
    int bh  = idx / NN, t = idx % NN;
    int b   = bh >> 2,  h = bh & 3;
    int v   = threadIdx.x;
    float of = g_of[idx*256 + v];
    float ob = g_ob[idx*256 + v];
    float sf = of*of, sb = ob*ob;
#pragma unroll
    for (int o = 16; o > 0; o >>= 1) {
        sf += __shfl_xor_sync(0xffffffffu, sf, o);
        sb += __shfl_xor_sync(0xffffffffu, sb, o);
    }
    int w = v >> 5, l = v & 31;
    if (l == 0) { red[w] = sf; red[8+w] = sb; }
    __syncthreads();
    float tf = 0.f, tb = 0.f;
#pragma unroll
    for (int i = 0; i < 8; ++i) { tf += red[i]; tb += red[8+i]; }
    float inf_ = rsqrtf(tf*(1.f/256.f) + 1e-5f);
    float inb_ = rsqrtf(tb*(1.f/256.f) + 1e-5f);
    float o = of*inf_*gnw[v] + ob*inb_*lnw[v];
    int gi = (b*NN + t)*1024 + h*256 + v;
    float val = o * g_g[gi];
    __nv_bfloat16 hh = __float2bfloat16(val);
    g_oc_h[gi] = hh;
    g_oc_l[gi] = __float2bfloat16(val - __bfloat162float(hh));
}

// ---------------------------------------------------------------------------
// launcher
// ---------------------------------------------------------------------------
extern "C" void kernel_launch(void* const* d_in, const int* in_sizes, int n_in,
                              void* d_out, int out_size)
{
    const float* x     = (const float*)d_in[0];
    const float* convw = (const float*)d_in[1];
    const float* qkvw  = (const float*)d_in[2];
    const float* gkw1  = (const float*)d_in[3];
    const float* gkw2  = (const float*)d_in[4];
    const float* gkb2  = (const float*)d_in[5];
    const float* gw    = (const float*)d_in[6];
    const float* gb    = (const float*)d_in[7];
    const float* gnw   = (const float*)d_in[8];
    const float* lnw   = (const float*)d_in[9];
    const float* ow    = (const float*)d_in[10];
    float* out = (float*)d_out;

    cudaFuncSetAttribute(gla_k, cudaFuncAttributeMaxDynamicSharedMemorySize, GLA_SMEM_BYTES);
    cudaFuncSetAttribute(gemm128_k<0>, cudaFuncAttributeMaxDynamicSharedMemorySize, GEMM_SMEM);
    cudaFuncSetAttribute(gemm128_k<1>, cudaFuncAttributeMaxDynamicSharedMemorySize, GEMM_SMEM);

    float *p_qkv, *p_g;
    __nv_bfloat16 *p_xs_h, *p_xs_l, *p_oc_h, *p_oc_l;
    __nv_bfloat16 *p_wq_h, *p_wq_l, *p_wg_h, *p_wg_l, *p_wo_h, *p_wo_l;
    cudaGetSymbolAddress((void**)&p_qkv,  g_qkv);
    cudaGetSymbolAddress((void**)&p_g,    g_g);
    cudaGetSymbolAddress((void**)&p_xs_h, g_xs_h);
    cudaGetSymbolAddress((void**)&p_xs_l, g_xs_l);
    cudaGetSymbolAddress((void**)&p_oc_h, g_oc_h);
    cudaGetSymbolAddress((void**)&p_oc_l, g_oc_l);
    cudaGetSymbolAddress((void**)&p_wq_h, g_wq_h);
    cudaGetSymbolAddress((void**)&p_wq_l, g_wq_l);
    cudaGetSymbolAddress((void**)&p_wg_h, g_wg_h);
    cudaGetSymbolAddress((void**)&p_wg_l, g_wg_l);
    cudaGetSymbolAddress((void**)&p_wo_h, g_wo_h);
    cudaGetSymbolAddress((void**)&p_wo_l, g_wo_l);

    // weight conversions (independent of conv)
    cvt_hilo_k<<<(2048*512 + 255)/256, 256>>>(qkvw, p_wq_h, p_wq_l, 2048*512);
    cvt_hilo_k<<<(1024*512 + 255)/256, 256>>>(gw,   p_wg_h, p_wg_l, 1024*512);
    cvt_hilo_k<<<(512*1024 + 255)/256, 256>>>(ow,   p_wo_h, p_wo_l, 512*1024);

    conv_silu_k<<<MROWS, 512>>>(x, convw);

    gemm128_k<0><<<dim3(2048/128, MROWS/128), 256, GEMM_SMEM>>>(p_xs_h, p_xs_l, p_wq_h, p_wq_l, nullptr, p_qkv, 2048, 512);
    gemm128_k<1><<<dim3(1024/128, MROWS/128), 256, GEMM_SMEM>>>(p_xs_h, p_xs_l, p_wg_h, p_wg_l, gb, p_g, 1024, 512);

    gk1_k<<<MROWS/64, 256>>>(gkw1);
    gk2_k<<<dim3(4, MROWS/64), 256>>>(gkw2, gkb2);
    gla_k<<<dim3(4, BB*NH, 2), 256, GLA_SMEM_BYTES>>>();
    combine_k<<<BB*NH*NN, 256>>>(gnw, lnw);

    gemm128_k<0><<<dim3(512/128, MROWS/128), 256, GEMM_SMEM>>>(p_oc_h, p_oc_l, p_wo_h, p_wo_l, nullptr, out, 512, 1024);
}

// round 9
// speedup vs baseline: 2.7235x; 1.8105x over previous
#include <cuda_runtime.h>
#include <cuda_bf16.h>
#include <math.h>
#include <stdint.h>

// ---------------------------------------------------------------------------
// Problem constants
// ---------------------------------------------------------------------------
#define BB     8
#define NN     3136
#define HH_    56
#define WW_    56
#define DM     512
#define NH     4
#define HQ     128
#define HV     256
#define CH     64
#define NCH    49
#define MROWS  (BB*NN)       // 25088

// ---------------------------------------------------------------------------
// Scratch
// ---------------------------------------------------------------------------
static __device__ float g_xs   [MROWS*DM];
static __device__ __nv_bfloat16 g_xs_h[MROWS*DM];
static __device__ __nv_bfloat16 g_xs_l[MROWS*DM];
static __device__ float g_qkv  [MROWS*2048];
static __device__ float g_g    [MROWS*1024];
static __device__ float g_gklat[MROWS*16];
static __device__ float g_gk   [MROWS*1024];
static __device__ float g_of   [MROWS*1024];
static __device__ float g_ob   [MROWS*1024];
static __device__ __nv_bfloat16 g_oc_h[MROWS*1024];
static __device__ __nv_bfloat16 g_oc_l[MROWS*1024];
static __device__ __nv_bfloat16 g_wq_h[2048*512], g_wq_l[2048*512];
static __device__ __nv_bfloat16 g_wg_h[1024*512], g_wg_l[1024*512];
static __device__ __nv_bfloat16 g_wo_h[512*1024], g_wo_l[512*1024];

__device__ __forceinline__ float sigm(float x){ return 1.f/(1.f+__expf(-x)); }

__device__ __forceinline__ uint32_t smem_u32(const void* p) {
    uint32_t a;
    asm("{ .reg .u64 t; cvta.to.shared.u64 t, %1; cvt.u32.u64 %0, t; }" : "=r"(a) : "l"(p));
    return a;
}
__device__ __forceinline__ void cp16(uint32_t dst, const void* src) {
    asm volatile("cp.async.cg.shared.global [%0], [%1], 16;" :: "r"(dst), "l"(src));
}
#define CP_COMMIT() asm volatile("cp.async.commit_group;" ::: "memory")
#define CP_WAIT0()  asm volatile("cp.async.wait_group 0;" ::: "memory")
#define CP_WAIT1()  asm volatile("cp.async.wait_group 1;" ::: "memory")

__device__ __forceinline__ void ldsm4(uint32_t* r, uint32_t addr) {
    asm volatile("ldmatrix.sync.aligned.m8n8.x4.shared.b16 {%0,%1,%2,%3}, [%4];"
        : "=r"(r[0]), "=r"(r[1]), "=r"(r[2]), "=r"(r[3]) : "r"(addr));
}
__device__ __forceinline__ void ldsm4t(uint32_t* r, uint32_t addr) {
    asm volatile("ldmatrix.sync.aligned.m8n8.x4.trans.shared.b16 {%0,%1,%2,%3}, [%4];"
        : "=r"(r[0]), "=r"(r[1]), "=r"(r[2]), "=r"(r[3]) : "r"(addr));
}
__device__ __forceinline__ void mma16816(float* c, const uint32_t* a, uint32_t b0, uint32_t b1) {
    asm volatile("mma.sync.aligned.m16n8k16.row.col.f32.bf16.bf16.f32 "
        "{%0,%1,%2,%3}, {%4,%5,%6,%7}, {%8,%9}, {%0,%1,%2,%3};"
        : "+f"(c[0]), "+f"(c[1]), "+f"(c[2]), "+f"(c[3])
        : "r"(a[0]), "r"(a[1]), "r"(a[2]), "r"(a[3]), "r"(b0), "r"(b1));
}

__device__ __forceinline__ uint32_t packbf2(float a, float b) {
    __nv_bfloat162 t;
    t.x = __float2bfloat16(a);
    t.y = __float2bfloat16(b);
    return *(uint32_t*)&t;
}

extern __shared__ char s_dyn[];

// ---------------------------------------------------------------------------
// 1) depthwise 3x3 conv + SiLU, emit fp32 + bf16 hi/lo
// ---------------------------------------------------------------------------
__global__ void __launch_bounds__(512) conv_silu_k(const float* __restrict__ x,
                                                   const float* __restrict__ w)
{
    int bn = blockIdx.x;
    int b  = bn / NN, n = bn % NN;
    int y  = n / WW_, xx = n % WW_;
    int c  = threadIdx.x;
    float wr[9];
#pragma unroll
    for (int i = 0; i < 9; ++i) wr[i] = w[c*9 + i];
    float acc = 0.f;
#pragma unroll
    for (int ky = 0; ky < 3; ++ky) {
        int yy = y + ky - 1;
        if (yy < 0 || yy >= HH_) continue;
#pragma unroll
        for (int kx = 0; kx < 3; ++kx) {
            int xc = xx + kx - 1;
            if (xc < 0 || xc >= WW_) continue;
            acc += x[(b*NN + yy*WW_ + xc)*DM + c] * wr[ky*3 + kx];
        }
    }
    float r = acc * sigm(acc);
    g_xs[bn*DM + c] = r;
    __nv_bfloat16 h = __float2bfloat16(r);
    g_xs_h[bn*DM + c] = h;
    g_xs_l[bn*DM + c] = __float2bfloat16(r - __bfloat162float(h));
}

// ---------------------------------------------------------------------------
// hi/lo conversion for weights
// ---------------------------------------------------------------------------
__global__ void __launch_bounds__(256) cvt_hilo_k(const float* __restrict__ s,
                                                  __nv_bfloat16* __restrict__ h,
                                                  __nv_bfloat16* __restrict__ l, int n)
{
    int i = blockIdx.x*256 + threadIdx.x;
    if (i < n) {
        float v = s[i];
        __nv_bfloat16 hh = __float2bfloat16(v);
        h[i] = hh;
        l[i] = __float2bfloat16(v - __bfloat162float(hh));
    }
}

// ---------------------------------------------------------------------------
// 2) bf16x3 GEMM (NT) via mma.sync m16n8k16 (passing since R7)
// ---------------------------------------------------------------------------
#define GEMM_SMEM (2*4*16384)

template<int EPI>
__global__ void __launch_bounds__(256, 1)
gemm128_k(const __nv_bfloat16* __restrict__ Ah, const __nv_bfloat16* __restrict__ Al,
          const __nv_bfloat16* __restrict__ Bh, const __nv_bfloat16* __restrict__ Bl,
          const float* __restrict__ bias, float* __restrict__ C, int Nc, int K)
{
    const int tid  = threadIdx.x;
    const int lane = tid & 31;
    const int wid  = tid >> 5;
    const int wm   = (wid & 3) * 32;
    const int wn   = (wid >> 2) * 64;
    const int n0 = blockIdx.x * 128, m0 = blockIdx.y * 128;
    const uint32_t sb = smem_u32(s_dyn);
    const int nk = K >> 6;

    float acc[2][8][4];
#pragma unroll
    for (int i = 0; i < 2; ++i)
#pragma unroll
        for (int j = 0; j < 8; ++j)
#pragma unroll
            for (int q = 0; q < 4; ++q) acc[i][j][q] = 0.f;

    auto load_chunk = [&](int kc) {
        uint32_t tb = sb + (kc & 1) * 65536;
        int kb = kc << 6;
#pragma unroll
        for (int it = 0; it < 4; ++it) {
            int i = tid + it*256;
            int row = i >> 3, seg = i & 7;
            uint32_t off = (uint32_t)(row*128 + seg*16);
            uint32_t sw = off ^ ((off >> 3) & 0x70);
            const __nv_bfloat16* pAh = Ah + (size_t)(m0 + row)*K + kb + seg*8;
            const __nv_bfloat16* pAl = Al + (size_t)(m0 + row)*K + kb + seg*8;
            const __nv_bfloat16* pBh = Bh + (size_t)(n0 + row)*K + kb + seg*8;
            const __nv_bfloat16* pBl = Bl + (size_t)(n0 + row)*K + kb + seg*8;
            cp16(tb +         sw, pAh);
            cp16(tb + 16384 + sw, pAl);
            cp16(tb + 32768 + sw, pBh);
            cp16(tb + 49152 + sw, pBl);
        }
    };

    load_chunk(0); CP_COMMIT();

    const int aRow = lane & 15;
    const int aKof = ((lane >> 4) & 1) * 16;
    const int bRowL = (lane & 7) + ((lane & 16) ? 8 : 0);
    const int bKof = (lane & 8) ? 16 : 0;

    for (int c = 0; c < nk; ++c) {
        if (c + 1 < nk) { load_chunk(c + 1); CP_COMMIT(); CP_WAIT1(); }
        else            { CP_WAIT0(); }
        __syncthreads();

        uint32_t tb = sb + (c & 1) * 65536;
#pragma unroll
        for (int ks = 0; ks < 4; ++ks) {
            const int kbyte = ks * 32;
            uint32_t aH[2][4], aL[2][4];
#pragma unroll
            for (int mt = 0; mt < 2; ++mt) {
                uint32_t off = (uint32_t)((wm + mt*16 + aRow) * 128 + kbyte + aKof);
                uint32_t sw = off ^ ((off >> 3) & 0x70);
                ldsm4(aH[mt], tb + sw);
                ldsm4(aL[mt], tb + 16384 + sw);
            }
#pragma unroll
            for (int ntp = 0; ntp < 4; ++ntp) {
                uint32_t off = (uint32_t)((wn + ntp*16 + bRowL) * 128 + kbyte + bKof);
                uint32_t sw = off ^ ((off >> 3) & 0x70);
                uint32_t bh[4], bl[4];
                ldsm4(bh, tb + 32768 + sw);
                ldsm4(bl, tb + 49152 + sw);
#pragma unroll
                for (int mt = 0; mt < 2; ++mt) {
                    mma16816(acc[mt][ntp*2+0], aH[mt], bh[0], bh[1]);
                    mma16816(acc[mt][ntp*2+1], aH[mt], bh[2], bh[3]);
                    mma16816(acc[mt][ntp*2+0], aH[mt], bl[0], bl[1]);
                    mma16816(acc[mt][ntp*2+1], aH[mt], bl[2], bl[3]);
                    mma16816(acc[mt][ntp*2+0], aL[mt], bh[0], bh[1]);
                    mma16816(acc[mt][ntp*2+1], aL[mt], bh[2], bh[3]);
                }
            }
        }
        __syncthreads();
    }

    const int rbase = m0 + wm + (lane >> 2);
    const int cbase = n0 + wn + (lane & 3) * 2;
#pragma unroll
    for (int mt = 0; mt < 2; ++mt) {
#pragma unroll
        for (int nt = 0; nt < 8; ++nt) {
            int col = cbase + nt*8;
#pragma unroll
            for (int half = 0; half < 2; ++half) {
                int row = rbase + mt*16 + half*8;
                float v0 = acc[mt][nt][half*2+0];
                float v1 = acc[mt][nt][half*2+1];
                if (EPI == 1) {
                    v0 += bias[col+0]; v0 *= sigm(v0);
                    v1 += bias[col+1]; v1 *= sigm(v1);
                }
                float2 vv; vv.x = v0; vv.y = v1;
                *(float2*)&C[(size_t)row*Nc + col] = vv;
            }
        }
    }
}

// ---------------------------------------------------------------------------
// 3) gk low-rank stage 1
// ---------------------------------------------------------------------------
__global__ void __launch_bounds__(256) gk1_k(const float* __restrict__ w1)
{
    __shared__ float w1s[16*DM];
    int tid = threadIdx.x;
    for (int i = tid; i < 16*DM; i += 256) w1s[i] = w1[i];
    __syncthreads();
    int m0 = blockIdx.x * 64;
    int j  = tid & 15, rg = tid >> 4;
    const float* xb = &g_xs[(m0 + rg*4)*DM];
    const float4* w4 = (const float4*)&w1s[j*DM];
    float a0 = 0.f, a1 = 0.f, a2 = 0.f, a3 = 0.f;
#pragma unroll 4
    for (int k = 0; k < DM/4; ++k) {
        float4 wv = w4[k];
        float4 x0 = *(const float4*)&xb[0*DM + k*4];
        float4 x1 = *(const float4*)&xb[1*DM + k*4];
        float4 x2 = *(const float4*)&xb[2*DM + k*4];
        float4 x3 = *(const float4*)&xb[3*DM + k*4];
        a0 += x0.x*wv.x + x0.y*wv.y + x0.z*wv.z + x0.w*wv.w;
        a1 += x1.x*wv.x + x1.y*wv.y + x1.z*wv.z + x1.w*wv.w;
        a2 += x2.x*wv.x + x2.y*wv.y + x2.z*wv.z + x2.w*wv.w;
        a3 += x3.x*wv.x + x3.y*wv.y + x3.z*wv.z + x3.w*wv.w;
    }
    g_gklat[(m0+rg*4+0)*16 + j] = a0;
    g_gklat[(m0+rg*4+1)*16 + j] = a1;
    g_gklat[(m0+rg*4+2)*16 + j] = a2;
    g_gklat[(m0+rg*4+3)*16 + j] = a3;
}

// ---------------------------------------------------------------------------
// 4) gk stage 2
// ---------------------------------------------------------------------------
__global__ void __launch_bounds__(256) gk2_k(const float* __restrict__ w2,
                                             const float* __restrict__ b2)
{
    __shared__ float lat[64*16];
    int m0 = blockIdx.y * 64;
    int j  = blockIdx.x * 256 + threadIdx.x;
    for (int i = threadIdx.x; i < 64*16; i += 256) lat[i] = g_gklat[m0*16 + i];
    __syncthreads();
    float w[16];
#pragma unroll
    for (int i = 0; i < 16; ++i) w[i] = w2[j*16 + i];
    float bb = b2[j];
    for (int r = 0; r < 64; ++r) {
        float xv = bb;
#pragma unroll
        for (int i = 0; i < 16; ++i) xv += lat[r*16 + i]*w[i];
        float ls = fminf(xv, 0.f) - log1pf(__expf(-fabsf(xv)));
        g_gk[(m0+r)*1024 + j] = ls * (1.f/16.f);
    }
}

// ---------------------------------------------------------------------------
// 5) Chunked GLA — tensorized (mma.sync bf16x3; state fp32 in smem)
//    grid (vs 4, bh 32, dir 2), 256 threads = 8 warps (4m x 2n)
// ---------------------------------------------------------------------------
#define OF_SG    0
#define OF_EBT   33792
#define OF_SF    34304
#define OF_QEH   69120
#define OF_QEL   86528
#define OF_KDH   103936
#define OF_KDL   121344
#define OF_VH    138752
#define OF_VL    147968
#define OF_AH    157184
#define OF_AL    166400
#define OF_SBH   175616
#define OF_SBL   194048
#define GLA_SMEM_BYTES 212480

__global__ void __launch_bounds__(256, 1) gla_k()
{
    char* sm = s_dyn;
    const uint32_t sb = smem_u32(sm);
    float* sg  = (float*)(sm + OF_SG);
    float* ebt = (float*)(sm + OF_EBT);
    float* Sf  = (float*)(sm + OF_SF);

    const int vs  = blockIdx.x;
    const int bh  = blockIdx.y;
    const int dir = blockIdx.z;
    const int b   = bh >> 2;
    const int h   = bh & 3;
    const int tid = threadIdx.x;
    const int lane = tid & 31;
    const int w    = tid >> 5;
    const float scale = 0.088388347648318447f;  // 128^-0.5

    for (int i = tid; i < 128*68; i += 256) Sf[i] = 0.f;
    __syncthreads();

    const int qoff = h*HQ;
    const int koff = 512 + h*HQ;
    const int voff = 1024 + h*HV + vs*64;
    const int goff = dir*512 + h*HQ;
    const int rowb = b*NN;
    float* const outp = dir ? g_ob : g_of;

    const int m0w = (w & 3) * 16;
    const int n0w = (w >> 2) * 32;
    const int m0u = (w & 3) * 32;
    const int aRow = lane & 15;
    const int aSel = ((lane >> 4) & 1) * 16;
    const int bRowL = (lane & 7) + ((lane & 16) ? 8 : 0);
    const int bKof  = (lane & 8) ? 16 : 0;
    const int vRow = (lane & 7) + ((lane >> 3) & 1) * 8;
    const int vSel = ((lane >> 4) & 1) * 16;
    const int tRowT = (lane & 7) + ((lane >> 4) & 1) * 8;
    const int tSelT = ((lane >> 3) & 1) * 16;
    const int g8 = lane >> 2;
    const int q2 = (lane & 3) * 2;

    for (int c = 0; c < NCH; ++c) {
        // ---- P0: load gk chunk -> sg (f32); load+convert v -> v_h/v_l ----
#pragma unroll
        for (int it = 0; it < 8; ++it) {
            int j = tid + it*256;
            int t = j >> 5, d4 = (j & 31) * 4;          // FIXED: 64 rows x 32 float4
            int tg = dir ? (NN-1 - (c*64 + t)) : (c*64 + t);
            *(float4*)&sg[t*132 + d4] = *(const float4*)&g_gk[(size_t)(rowb+tg)*1024 + goff + d4];
        }
#pragma unroll
        for (int it = 0; it < 4; ++it) {
            int j = tid + it*256;
            int s = j >> 4, c4 = (j & 15) * 4;
            int tg = dir ? (NN-1 - (c*64 + s)) : (c*64 + s);
            float4 vv = *(const float4*)&g_qkv[(size_t)(rowb+tg)*2048 + voff + c4];
            __nv_bfloat16 h0 = __float2bfloat16(vv.x), h1 = __float2bfloat16(vv.y);
            __nv_bfloat16 h2 = __float2bfloat16(vv.z), h3 = __float2bfloat16(vv.w);
            uint2 hw, lw;
            hw.x = packbf2(vv.x, vv.y); hw.y = packbf2(vv.z, vv.w);
            lw.x = packbf2(vv.x - __bfloat162float(h0), vv.y - __bfloat162float(h1));
            lw.y = packbf2(vv.z - __bfloat162float(h2), vv.w - __bfloat162float(h3));
            *(uint2*)(sm + OF_VH + s*144 + c4*2) = hw;
            *(uint2*)(sm + OF_VL + s*144 + c4*2) = lw;
        }
        __syncthreads();

        // ---- P1: cumsum along t ----
        if (tid < 128) {
            int d = tid;
            float run = 0.f;
#pragma unroll
            for (int blk = 0; blk < 4; ++blk) {
                float r[16];
#pragma unroll
                for (int i = 0; i < 16; ++i) r[i] = sg[(blk*16+i)*132 + d];
#pragma unroll
                for (int i = 0; i < 16; ++i) { run += r[i]; r[i] = run; }
#pragma unroll
                for (int i = 0; i < 16; ++i) sg[(blk*16+i)*132 + d] = r[i];
            }
            ebt[d] = __expf(run);
        }
        __syncthreads();

        // ---- P2: qe/kd conversion + S -> bf16 split ----
#pragma unroll
        for (int it = 0; it < 8; ++it) {
            int j = tid + it*256;
            int t = j >> 5, d4 = (j & 31) * 4;          // FIXED: 64 rows x 32 float4
            int tg = dir ? (NN-1 - (c*64 + t)) : (c*64 + t);
            size_t r = (size_t)(rowb+tg)*2048;
            float4 qv = *(const float4*)&g_qkv[r + qoff + d4];
            float4 kv = *(const float4*)&g_qkv[r + koff + d4];
            float4 bv = *(float4*)&sg[t*132 + d4];
            float e0 = __expf(bv.x), e1 = __expf(bv.y), e2 = __expf(bv.z), e3 = __expf(bv.w);
            float f0 = __expf(-bv.x), f1 = __expf(-bv.y), f2 = __expf(-bv.z), f3 = __expf(-bv.w);
            float q0 = qv.x*e0*scale, q1 = qv.y*e1*scale, q2v = qv.z*e2*scale, q3 = qv.w*e3*scale;
            float k0 = kv.x*f0, k1 = kv.y*f1, k2 = kv.z*f2, k3 = kv.w*f3;
            __nv_bfloat16 qh0 = __float2bfloat16(q0), qh1 = __float2bfloat16(q1);
            __nv_bfloat16 qh2 = __float2bfloat16(q2v), qh3 = __float2bfloat16(q3);
            __nv_bfloat16 kh0 = __float2bfloat16(k0), kh1 = __float2bfloat16(k1);
            __nv_bfloat16 kh2 = __float2bfloat16(k2), kh3 = __float2bfloat16(k3);
            uint2 qhw, qlw, khw, klw;
            qhw.x = packbf2(q0, q1); qhw.y = packbf2(q2v, q3);
            qlw.x = packbf2(q0 - __bfloat162float(qh0), q1 - __bfloat162float(qh1));
            qlw.y = packbf2(q2v - __bfloat162float(qh2), q3 - __bfloat162float(qh3));
            khw.x = packbf2(k0, k1); khw.y = packbf2(k2, k3);
            klw.x = packbf2(k0 - __bfloat162float(kh0), k1 - __bfloat162float(kh1));
            klw.y = packbf2(k2 - __bfloat162float(kh2), k3 - __bfloat162float(kh3));
            *(uint2*)(sm + OF_QEH + t*272 + d4*2) = qhw;
            *(uint2*)(sm + OF_QEL + t*272 + d4*2) = qlw;
            *(uint2*)(sm + OF_KDH + t*272 + d4*2) = khw;
            *(uint2*)(sm + OF_KDL + t*272 + d4*2) = klw;
        }
#pragma unroll
        for (int it = 0; it < 16; ++it) {
            int j = tid + it*256;
            int d = j >> 5, c2 = (j & 31) * 2;
            float2 sv = *(float2*)&Sf[d*68 + c2];
            __nv_bfloat16 s0 = __float2bfloat16(sv.x), s1 = __float2bfloat16(sv.y);
            *(uint32_t*)(sm + OF_SBH + d*144 + c2*2) = packbf2(sv.x, sv.y);
            *(uint32_t*)(sm + OF_SBL + d*144 + c2*2) =
                packbf2(sv.x - __bfloat162float(s0), sv.y - __bfloat162float(s1));
        }
        __syncthreads();

        // ---- P3: A = qe @ kd^T (64x64, k=128), mask, store bf16 hi/lo ----
        {
            float acc[4][4];
#pragma unroll
            for (int f = 0; f < 4; ++f)
#pragma unroll
                for (int j = 0; j < 4; ++j) acc[f][j] = 0.f;
#pragma unroll
            for (int ks = 0; ks < 8; ++ks) {
                int kb = ks * 32;
                uint32_t aH[4], aL[4];
                ldsm4(aH, sb + OF_QEH + (m0w + aRow)*272 + kb + aSel);
                ldsm4(aL, sb + OF_QEL + (m0w + aRow)*272 + kb + aSel);
                uint32_t bh0[4], bh1[4], bl0[4], bl1[4];
                ldsm4(bh0, sb + OF_KDH + (n0w + bRowL)*272 + kb + bKof);
                ldsm4(bh1, sb + OF_KDH + (n0w + 16 + bRowL)*272 + kb + bKof);
                ldsm4(bl0, sb + OF_KDL + (n0w + bRowL)*272 + kb + bKof);
                ldsm4(bl1, sb + OF_KDL + (n0w + 16 + bRowL)*272 + kb + bKof);
                mma16816(acc[0], aH, bh0[0], bh0[1]);
                mma16816(acc[1], aH, bh0[2], bh0[3]);
                mma16816(acc[2], aH, bh1[0], bh1[1]);
                mma16816(acc[3], aH, bh1[2], bh1[3]);
                mma16816(acc[0], aH, bl0[0], bl0[1]);
                mma16816(acc[1], aH, bl0[2], bl0[3]);
                mma16816(acc[2], aH, bl1[0], bl1[1]);
                mma16816(acc[3], aH, bl1[2], bl1[3]);
                mma16816(acc[0], aL, bh0[0], bh0[1]);
                mma16816(acc[1], aL, bh0[2], bh0[3]);
                mma16816(acc[2], aL, bh1[0], bh1[1]);
                mma16816(acc[3], aL, bh1[2], bh1[3]);
            }
#pragma unroll
            for (int f = 0; f < 4; ++f) {
                int scol = n0w + f*8 + q2;
#pragma unroll
                for (int hh = 0; hh < 2; ++hh) {
                    int t = m0w + g8 + hh*8;
                    float v0 = (scol     <= t) ? acc[f][hh*2+0] : 0.f;
                    float v1 = (scol + 1 <= t) ? acc[f][hh*2+1] : 0.f;
                    __nv_bfloat16 a0 = __float2bfloat16(v0), a1 = __float2bfloat16(v1);
                    *(uint32_t*)(sm + OF_AH + t*144 + scol*2) = packbf2(v0, v1);
                    *(uint32_t*)(sm + OF_AL + t*144 + scol*2) =
                        packbf2(v0 - __bfloat162float(a0), v1 - __bfloat162float(a1));
                }
            }
        }
        __syncthreads();

        // ---- P4: o = A@v + qe@S -> gmem ; U = kd^T @ v ; S update ----
        {
            float acc[4][4];
#pragma unroll
            for (int f = 0; f < 4; ++f)
#pragma unroll
                for (int j = 0; j < 4; ++j) acc[f][j] = 0.f;
            // A @ v  (k = s = 64)
#pragma unroll
            for (int ks = 0; ks < 4; ++ks) {
                int kb = ks * 32;
                uint32_t aH[4], aL[4];
                ldsm4(aH, sb + OF_AH + (m0w + aRow)*144 + kb + aSel);
                ldsm4(aL, sb + OF_AL + (m0w + aRow)*144 + kb + aSel);
                uint32_t b0h[4], b1h[4], b0l[4], b1l[4];
                uint32_t vr = (ks*16 + vRow)*144;
                ldsm4t(b0h, sb + OF_VH + vr + n0w*2 + vSel);
                ldsm4t(b1h, sb + OF_VH + vr + (n0w + 16)*2 + vSel);
                ldsm4t(b0l, sb + OF_VL + vr + n0w*2 + vSel);
                ldsm4t(b1l, sb + OF_VL + vr + (n0w + 16)*2 + vSel);
                mma16816(acc[0], aH, b0h[0], b0h[1]);
                mma16816(acc[1], aH, b0h[2], b0h[3]);
                mma16816(acc[2], aH, b1h[0], b1h[1]);
                mma16816(acc[3], aH, b1h[2], b1h[3]);
                mma16816(acc[0], aH, b0l[0], b0l[1]);
                mma16816(acc[1], aH, b0l[2], b0l[3]);
                mma16816(acc[2], aH, b1l[0], b1l[1]);
                mma16816(acc[3], aH, b1l[2], b1l[3]);
                mma16816(acc[0], aL, b0h[0], b0h[1]);
                mma16816(acc[1], aL, b0h[2], b0h[3]);
                mma16816(acc[2], aL, b1h[0], b1h[1]);
                mma16816(acc[3], aL, b1h[2], b1h[3]);
            }
            // qe @ S  (k = d = 128)
#pragma unroll
            for (int ks = 0; ks < 8; ++ks) {
                int kb = ks * 32;
                uint32_t aH[4], aL[4];
                ldsm4(aH, sb + OF_QEH + (m0w + aRow)*272 + kb + aSel);
                ldsm4(aL, sb + OF_QEL + (m0w + aRow)*272 + kb + aSel);
                uint32_t b0h[4], b1h[4], b0l[4], b1l[4];
                uint32_t sr = (ks*16 + vRow)*144;
                ldsm4t(b0h, sb + OF_SBH + sr + n0w*2 + vSel);
                ldsm4t(b1h, sb + OF_SBH + sr + (n0w + 16)*2 + vSel);
                ldsm4t(b0l, sb + OF_SBL + sr + n0w*2 + vSel);
                ldsm4t(b1l, sb + OF_SBL + sr + (n0w + 16)*2 + vSel);
                mma16816(acc[0], aH, b0h[0], b0h[1]);
                mma16816(acc[1], aH, b0h[2], b0h[3]);
                mma16816(acc[2], aH, b1h[0], b1h[1]);
                mma16816(acc[3], aH, b1h[2], b1h[3]);
                mma16816(acc[0], aH, b0l[0], b0l[1]);
                mma16816(acc[1], aH, b0l[2], b0l[3]);
                mma16816(acc[2], aH, b1l[0], b1l[1]);
                mma16816(acc[3], aH, b1l[2], b1l[3]);
                mma16816(acc[0], aL, b0h[0], b0h[1]);
                mma16816(acc[1], aL, b0h[2], b0h[3]);
                mma16816(acc[2], aL, b1h[0], b1h[1]);
                mma16816(acc[3], aL, b1h[2], b1h[3]);
            }
            // write o
#pragma unroll
            for (int f = 0; f < 4; ++f) {
                int col = n0w + f*8 + q2;
#pragma unroll
                for (int hh = 0; hh < 2; ++hh) {
                    int t = m0w + g8 + hh*8;
                    int tg = dir ? (NN-1 - (c*64 + t)) : (c*64 + t);
                    float2 vv; vv.x = acc[f][hh*2+0]; vv.y = acc[f][hh*2+1];
                    *(float2*)&outp[(size_t)(bh*NN + tg)*256 + vs*64 + col] = vv;
                }
            }
            // U = kd^T @ v  (128x64, k=t=64)
            float au[2][4][4];
#pragma unroll
            for (int mt = 0; mt < 2; ++mt)
#pragma unroll
                for (int f = 0; f < 4; ++f)
#pragma unroll
                    for (int j = 0; j < 4; ++j) au[mt][f][j] = 0.f;
#pragma unroll
            for (int ks = 0; ks < 4; ++ks) {
                uint32_t aTh[2][4], aTl[2][4];
                uint32_t tr = (ks*16 + tRowT)*272;
#pragma unroll
                for (int mt = 0; mt < 2; ++mt) {
                    uint32_t dby = (m0u + mt*16)*2 + tSelT;
                    ldsm4t(aTh[mt], sb + OF_KDH + tr + dby);
                    ldsm4t(aTl[mt], sb + OF_KDL + tr + dby);
                }
                uint32_t b0h[4], b1h[4], b0l[4], b1l[4];
                uint32_t vr = (ks*16 + vRow)*144;
                ldsm4t(b0h, sb + OF_VH + vr + n0w*2 + vSel);
                ldsm4t(b1h, sb + OF_VH + vr + (n0w + 16)*2 + vSel);
                ldsm4t(b0l, sb + OF_VL + vr + n0w*2 + vSel);
                ldsm4t(b1l, sb + OF_VL + vr + (n0w + 16)*2 + vSel);
#pragma unroll
                for (int mt = 0; mt < 2; ++mt) {
                    mma16816(au[mt][0], aTh[mt], b0h[0], b0h[1]);
                    mma16816(au[mt][1], aTh[mt], b0h[2], b0h[3]);
                    mma16816(au[mt][2], aTh[mt], b1h[0], b1h[1]);
                    mma16816(au[mt][3], aTh[mt], b1h[2], b1h[3]);
                    mma16816(au[mt][0], aTh[mt], b0l[0], b0l[1]);
                    mma16816(au[mt][1], aTh[mt], b0l[2], b0l[3]);
                    mma16816(au[mt][2], aTh[mt], b1l[0], b1l[1]);
                    mma16816(au[mt][3], aTh[mt], b1l[2], b1l[3]);
                    mma16816(au[mt][0], aTl[mt], b0h[0], b0h[1]);
                    mma16816(au[mt][1], aTl[mt], b0h[2], b0h[3]);
                    mma16816(au[mt][2], aTl[mt], b1h[0], b1h[1]);
                    mma16816(au[mt][3], aTl[mt], b1h[2], b1h[3]);
                }
            }
            // S = exp(btot) * (S + U)
#pragma unroll
            for (int mt = 0; mt < 2; ++mt) {
#pragma unroll
                for (int f = 0; f < 4; ++f) {
                    int vc = n0w + f*8 + q2;
#pragma unroll
                    for (int hh = 0; hh < 2; ++hh) {
                        int d = m0u + mt*16 + g8 + hh*8;
                        float e = ebt[d];
                        float2 s = *(float2*)&Sf[d*68 + vc];
                        s.x = e * (s.x + au[mt][f][hh*2+0]);
                        s.y = e * (s.y + au[mt][f][hh*2+1]);
                        *(float2*)&Sf[d*68 + vc] = s;
                    }
                }
            }
        }
        __syncthreads();
    }
}

// ---------------------------------------------------------------------------
// 6) combine
// ---------------------------------------------------------------------------
__global__ void __launch_bounds__(256) combine_k(const float* __restrict__ gnw,
                                                 const float* __restrict__ lnw)
{
    __shared__ float red[16];
    int idx = blockIdx.x;
    int bh  = idx / NN, t = idx % NN;
    int b   = bh >> 2,  h = bh & 3;
    int v   = threadIdx.x;
    float of = g_of[(size_t)idx*256 + v];
    float ob = g_ob[(size_t)idx*256 + v];
    float sf = of*of, sb = ob*ob;
#pragma unroll
    for (int o = 16; o > 0; o >>= 1) {
        sf += __shfl_xor_sync(0xffffffffu, sf, o);
        sb += __shfl_xor_sync(0xffffffffu, sb, o);
    }
    int w = v >> 5, l = v & 31;
    if (l == 0) { red[w] = sf; red[8+w] = sb; }
    __syncthreads();
    float tf = 0.f, tb = 0.f;
#pragma unroll
    for (int i = 0; i < 8; ++i) { tf += red[i]; tb += red[8+i]; }
    float inf_ = rsqrtf(tf*(1.f/256.f) + 1e-5f);
    float inb_ = rsqrtf(tb*(1.f/256.f) + 1e-5f);
    float o = of*inf_*gnw[v] + ob*inb_*lnw[v];
    int gi = (b*NN + t)*1024 + h*256 + v;
    float val = o * g_g[gi];
    __nv_bfloat16 hh = __float2bfloat16(val);
    g_oc_h[gi] = hh;
    g_oc_l[gi] = __float2bfloat16(val - __bfloat162float(hh));
}

// ---------------------------------------------------------------------------
// launcher
// ---------------------------------------------------------------------------
extern "C" void kernel_launch(void* const* d_in, const int* in_sizes, int n_in,
                              void* d_out, int out_size)
{
    const float* x     = (const float*)d_in[0];
    const float* convw = (const float*)d_in[1];
    const float* qkvw  = (const float*)d_in[2];
    const float* gkw1  = (const float*)d_in[3];
    const float* gkw2  = (const float*)d_in[4];
    const float* gkb2  = (const float*)d_in[5];
    const float* gw    = (const float*)d_in[6];
    const float* gb    = (const float*)d_in[7];
    const float* gnw   = (const float*)d_in[8];
    const float* lnw   = (const float*)d_in[9];
    const float* ow    = (const float*)d_in[10];
    float* out = (float*)d_out;

    cudaFuncSetAttribute(gla_k, cudaFuncAttributeMaxDynamicSharedMemorySize, GLA_SMEM_BYTES);
    cudaFuncSetAttribute(gemm128_k<0>, cudaFuncAttributeMaxDynamicSharedMemorySize, GEMM_SMEM);
    cudaFuncSetAttribute(gemm128_k<1>, cudaFuncAttributeMaxDynamicSharedMemorySize, GEMM_SMEM);

    float *p_qkv, *p_g;
    __nv_bfloat16 *p_xs_h, *p_xs_l, *p_oc_h, *p_oc_l;
    __nv_bfloat16 *p_wq_h, *p_wq_l, *p_wg_h, *p_wg_l, *p_wo_h, *p_wo_l;
    cudaGetSymbolAddress((void**)&p_qkv,  g_qkv);
    cudaGetSymbolAddress((void**)&p_g,    g_g);
    cudaGetSymbolAddress((void**)&p_xs_h, g_xs_h);
    cudaGetSymbolAddress((void**)&p_xs_l, g_xs_l);
    cudaGetSymbolAddress((void**)&p_oc_h, g_oc_h);
    cudaGetSymbolAddress((void**)&p_oc_l, g_oc_l);
    cudaGetSymbolAddress((void**)&p_wq_h, g_wq_h);
    cudaGetSymbolAddress((void**)&p_wq_l, g_wq_l);
    cudaGetSymbolAddress((void**)&p_wg_h, g_wg_h);
    cudaGetSymbolAddress((void**)&p_wg_l, g_wg_l);
    cudaGetSymbolAddress((void**)&p_wo_h, g_wo_h);
    cudaGetSymbolAddress((void**)&p_wo_l, g_wo_l);

    cvt_hilo_k<<<(2048*512 + 255)/256, 256>>>(qkvw, p_wq_h, p_wq_l, 2048*512);
    cvt_hilo_k<<<(1024*512 + 255)/256, 256>>>(gw,   p_wg_h, p_wg_l, 1024*512);
    cvt_hilo_k<<<(512*1024 + 255)/256, 256>>>(ow,   p_wo_h, p_wo_l, 512*1024);

    conv_silu_k<<<MROWS, 512>>>(x, convw);

    gemm128_k<0><<<dim3(2048/128, MROWS/128), 256, GEMM_SMEM>>>(p_xs_h, p_xs_l, p_wq_h, p_wq_l, nullptr, p_qkv, 2048, 512);
    gemm128_k<1><<<dim3(1024/128, MROWS/128), 256, GEMM_SMEM>>>(p_xs_h, p_xs_l, p_wg_h, p_wg_l, gb, p_g, 1024, 512);

    gk1_k<<<MROWS/64, 256>>>(gkw1);
    gk2_k<<<dim3(4, MROWS/64), 256>>>(gkw2, gkb2);
    gla_k<<<dim3(4, BB*NH, 2), 256, GLA_SMEM_BYTES>>>();
    combine_k<<<BB*NH*NN, 256>>>(gnw, lnw);

    gemm128_k<0><<<dim3(512/128, MROWS/128), 256, GEMM_SMEM>>>(p_oc_h, p_oc_l, p_wo_h, p_wo_l, nullptr, out, 512, 1024);
}